// round 16
// baseline (speedup 1.0000x reference)
#include <cuda_runtime.h>
#include <cuda_fp16.h>
#include <cstdint>

// V=32000, S=64, T=64, B=64, E=128, EH=256, DH=256
__device__ float g_scratch[15200000];
__device__ __half g_h[32400000];     // Bh[28672000], Ah[3670016]
__device__ unsigned g_bar[4];        // enc dir0, enc dir1, enc final, dec

__device__ __forceinline__ float sigmoidf_(float x) { return 1.0f / (1.0f + __expf(-x)); }
__device__ __forceinline__ float tanh_fast(float x) {
    float y; asm("tanh.approx.f32 %0, %1;" : "=f"(y) : "f"(x)); return y;
}
__device__ __forceinline__ uint32_t smem_u32(const void* p) {
    uint32_t a;
    asm("{ .reg .u64 t; cvta.to.shared.u64 t, %1; cvt.u32.u64 %0, t; }" : "=r"(a) : "l"(p));
    return a;
}
#define CP_ASYNC16(dst, src) \
    asm volatile("cp.async.cg.shared.global [%0], [%1], 16;" :: "r"(dst), "l"(src) : "memory")
#define CP_ASYNC_COMMIT() asm volatile("cp.async.commit_group;" ::: "memory")
#define CP_ASYNC_WAIT2()  asm volatile("cp.async.wait_group 2;" ::: "memory")
#define LDSM_X4(r, addr) \
    asm volatile("ldmatrix.sync.aligned.m8n8.x4.shared.b16 {%0,%1,%2,%3}, [%4];" \
        : "=r"((r)[0]), "=r"((r)[1]), "=r"((r)[2]), "=r"((r)[3]) : "r"(addr))
#define MMA_F16(c, a, b) \
    asm volatile("mma.sync.aligned.m16n8k16.row.col.f32.f16.f16.f32 " \
        "{%0,%1,%2,%3}, {%4,%5,%6,%7}, {%8,%9}, {%0,%1,%2,%3};" \
        : "+f"((c)[0]), "+f"((c)[1]), "+f"((c)[2]), "+f"((c)[3]) \
        : "r"((a)[0]), "r"((a)[1]), "r"((a)[2]), "r"((a)[3]), "r"((b)[0]), "r"((b)[1]))

// NOTE: parameter names must not collide with float4 field names (.x/.y/.z/.w)
#define DOT4(acc, v_, w_) \
    (acc) += (v_).x*(w_).x + (v_).y*(w_).y + (v_).z*(w_).z + (v_).w*(w_).w

// grid-wide barrier (monotonic counter; reset each replay by memset node)
__device__ __forceinline__ void grid_bar(unsigned* cnt, unsigned target) {
    __syncthreads();
    if (threadIdx.x == 0) {
        asm volatile("red.release.gpu.global.add.u32 [%0], %1;" :: "l"(cnt), "r"(1u) : "memory");
        unsigned v;
        do {
            asm volatile("ld.acquire.gpu.global.u32 %0, [%1];" : "=r"(v) : "l"(cnt) : "memory");
            if (v < target) __nanosleep(64);
        } while (v < target);
    }
    __syncthreads();
}

__global__ void zero_out_kernel(float* __restrict__ p) {
    p[blockIdx.x * 256 + threadIdx.x] = 0.f;
}

// ---------------- prologue: pack4 transposes + embed + fc_W->fp16 ----------------
// P[(e>>2)*(ncol*4) + col*4 + (e&3)] = src[col*ld + off + e]
__device__ __forceinline__ void pack4_job(const float* __restrict__ src, float* __restrict__ dst,
                                          int ncol, int ne, int ld, int off, int blk, int tid) {
    int idx = blk * 256 + tid;
    if (idx >= ncol * ne) return;
    int col = idx / ne, e = idx - col * ne;
    dst[(e >> 2) * (ncol * 4) + col * 4 + (e & 3)] = src[(size_t)col * ld + off + e];
}

__global__ void prologue_kernel(
    const float* __restrict__ fc_W, __half* __restrict__ Bh,
    const int* __restrict__ src, const float* __restrict__ enc_emb, float* __restrict__ emb,
    const float* __restrict__ enc_Whh_f, float* __restrict__ WhhP_f,
    const float* __restrict__ enc_Whh_b, float* __restrict__ WhhP_b,
    const float* __restrict__ dec_Whh, float* __restrict__ dWhhP,
    const float* __restrict__ dec_Wih, float* __restrict__ dWihP,
    const float* __restrict__ attn_W, float* __restrict__ WhP,
    const float* __restrict__ enc_fc_W, float* __restrict__ fcP,
    float* __restrict__ WeP)
{
    int blk = blockIdx.x, tid = threadIdx.x;
    if (blk < 112000) {
        long i = (long)blk * 256 + tid;
        Bh[i] = __float2half(fc_W[i]);
        return;
    }
    blk -= 112000;
    if (blk < 2048) {
        int e = blk * 256 + tid;
        int sb = e >> 7, c = e & 127;
        emb[e] = enc_emb[(size_t)src[sb] * 128 + c];
        return;
    }
    blk -= 2048;
    if (blk < 768)  { pack4_job(enc_Whh_f, WhhP_f, 768, 256, 256, 0, blk, tid); return; } blk -= 768;
    if (blk < 768)  { pack4_job(enc_Whh_b, WhhP_b, 768, 256, 256, 0, blk, tid); return; } blk -= 768;
    if (blk < 768)  { pack4_job(dec_Whh,  dWhhP,  768, 256, 256, 0, blk, tid); return; } blk -= 768;
    if (blk < 1920) { pack4_job(dec_Wih,  dWihP,  768, 640, 640, 0, blk, tid); return; } blk -= 1920;
    if (blk < 256)  { pack4_job(attn_W,   WhP,    256, 256, 768, 0, blk, tid); return; } blk -= 256;
    if (blk < 512)  { pack4_job(enc_fc_W, fcP,    256, 512, 512, 0, blk, tid); return; } blk -= 512;
    pack4_job(attn_W, WeP, 256, 512, 768, 256, blk, tid);   // W_e
}

// ---------------- fp32 sgemm (both encoder input-gate GEMMs) ----------------
__device__ __forceinline__ void sgemm_body(
    int M, int N, int K,
    const float* __restrict__ A, int lda,
    const float* __restrict__ Bm, int ldb,
    const float* __restrict__ bias, float* __restrict__ C, int ldc,
    float As[8][64], float Bs[8][128])
{
    const int tid = threadIdx.x;
    const int m0 = blockIdx.y * 64, n0 = blockIdx.x * 128;
    const int tx = tid & 15, ty = tid >> 4;
    const int ar = tid >> 2, ac = tid & 3;
    const int br = tid >> 1, bc = tid & 1;
    const float* Ap = A + (size_t)(m0 + ar) * lda + ac * 2;
    const float* Bp = Bm + (size_t)(n0 + br) * ldb + bc * 4;

    float acc[4][8];
#pragma unroll
    for (int i = 0; i < 4; i++)
#pragma unroll
        for (int j = 0; j < 8; j++) acc[i][j] = 0.f;

    for (int k0 = 0; k0 < K; k0 += 8) {
        float2 av = *(const float2*)(Ap + k0);
        float4 bv = *(const float4*)(Bp + k0);
        As[ac * 2 + 0][ar] = av.x; As[ac * 2 + 1][ar] = av.y;
        Bs[bc * 4 + 0][br] = bv.x; Bs[bc * 4 + 1][br] = bv.y;
        Bs[bc * 4 + 2][br] = bv.z; Bs[bc * 4 + 3][br] = bv.w;
        __syncthreads();
#pragma unroll
        for (int k = 0; k < 8; k++) {
            float a[4], bb[8];
            *(float4*)a = *(const float4*)&As[k][ty * 4];
            *(float4*)(bb + 0) = *(const float4*)&Bs[k][tx * 8 + 0];
            *(float4*)(bb + 4) = *(const float4*)&Bs[k][tx * 8 + 4];
#pragma unroll
            for (int i = 0; i < 4; i++)
#pragma unroll
                for (int j = 0; j < 8; j++) acc[i][j] += a[i] * bb[j];
        }
        __syncthreads();
    }
    const float* bp = bias + n0 + tx * 8;
#pragma unroll
    for (int i = 0; i < 4; i++) {
        float* cp = C + (size_t)(m0 + ty * 4 + i) * ldc + n0 + tx * 8;
#pragma unroll
        for (int q = 0; q < 8; q++) cp[q] = acc[i][q] + bp[q];
    }
}

__global__ __launch_bounds__(256) void sgemm_gi_kernel(
    const float* A, const float* W0, const float* W1,
    const float* b0, const float* b1, float* C0, float* C1)
{
    __shared__ float As[8][64], Bs[8][128];
    if (blockIdx.z == 0) sgemm_body(4096, 768, 128, A, 128, W0, 128, b0, C0, 768, As, Bs);
    else                 sgemm_body(4096, 768, 128, A, 128, W1, 128, b1, C1, 768, As, Bs);
}

// ---------------- persistent encoder: 64 steps both dirs + enc_proj tail ----------------
__global__ __launch_bounds__(256, 1) void enc_fused_kernel(
    const float* __restrict__ WhhP_f, const float* __restrict__ WhhP_b,
    const float* __restrict__ bhh_f, const float* __restrict__ bhh_b,
    const float* __restrict__ gi_f, const float* __restrict__ gi_b,
    float* __restrict__ h_enc, float* __restrict__ enc_outs,
    const float* __restrict__ WeP, const float* __restrict__ attn_b,
    float* __restrict__ enc_proj, unsigned* bar)
{
    const int blk = blockIdx.x, tid = threadIdx.x;
    const int dir = blk >> 6, rest = blk & 63, jg = rest & 7, bg = rest >> 3;
    const int bl = tid >> 5, jl = tid & 31;
    const int b = bg * 8 + bl, j = jg * 32 + jl;
    const float4* Wp4 = (const float4*)(dir ? WhhP_b : WhhP_f);
    const float* bhh = dir ? bhh_b : bhh_f;
    const float* gibase = dir ? gi_b : gi_f;
    __shared__ float4 hs4[8][64];
    __shared__ float4 shp4[16][128];

    unsigned* dbar = bar + dir;
    h_enc[(dir * 2 + 0) * 16384 + b * 256 + j] = 0.f;
    unsigned tgt = 64;
    grid_bar(dbar, tgt); tgt += 64;

    const float bh0 = bhh[j], bh1 = bhh[256 + j], bh2 = bhh[512 + j];

    for (int t = 0; t < 64; t++) {
        const float4* hprev4 = (const float4*)(h_enc + (dir * 2 + (t & 1)) * 16384);
        for (int i = tid; i < 512; i += 256)
            hs4[i >> 6][i & 63] = __ldcg(&hprev4[(bg * 8 + (i >> 6)) * 64 + (i & 63)]);
        __syncthreads();

        float a0 = bh0, a1 = bh1, a2 = bh2;
#pragma unroll 8
        for (int e4 = 0; e4 < 64; e4++) {
            float4 h = hs4[bl][e4];
            float4 w0 = Wp4[e4 * 768 + j];
            float4 w1 = Wp4[e4 * 768 + 256 + j];
            float4 w2 = Wp4[e4 * 768 + 512 + j];
            DOT4(a0, h, w0); DOT4(a1, h, w1); DOT4(a2, h, w2);
        }
        int tt = dir ? (63 - t) : t;
        const float* gi = gibase + ((size_t)tt * 64 + b) * 768;
        float r = sigmoidf_(gi[j] + a0);
        float z = sigmoidf_(gi[256 + j] + a1);
        float n = tanhf(gi[512 + j] + r * a2);
        float h2 = (1.f - z) * n + z * ((const float*)hs4)[bl * 256 + j];
        h_enc[(dir * 2 + ((t + 1) & 1)) * 16384 + b * 256 + j] = h2;
        enc_outs[((size_t)tt * 64 + b) * 512 + dir * 256 + j] = h2;
        grid_bar(dbar, tgt); tgt += 64;
    }

    // both dirs must finish before the enc_proj tail reads enc_outs
    grid_bar(bar + 2, 128);

    // tail: enc_proj[r, c] = enc_outs[r,:] @ W_e[c,:] + attn_b[c]; 32 rows/block
    const float4* eo4 = (const float4*)enc_outs;
    const float4* We4 = (const float4*)WeP;
    const float ab = attn_b[tid];
    for (int chunk = 0; chunk < 2; chunk++) {
        int r0 = blk * 32 + chunk * 16;
        for (int i = tid; i < 2048; i += 256)
            shp4[i >> 7][i & 127] = __ldcg(&eo4[(size_t)(r0 + (i >> 7)) * 128 + (i & 127)]);
        __syncthreads();
        float a16[16];
#pragma unroll
        for (int q = 0; q < 16; q++) a16[q] = ab;
#pragma unroll 4
        for (int e4 = 0; e4 < 128; e4++) {
            float4 w = We4[e4 * 256 + tid];
#pragma unroll
            for (int q = 0; q < 16; q++) DOT4(a16[q], shp4[q][e4], w);
        }
#pragma unroll
        for (int q = 0; q < 16; q++)
            enc_proj[(size_t)(r0 + q) * 256 + tid] = a16[q];
        __syncthreads();
    }
}

// ---------------- persistent decoder: enc_fc init + 63 steps + fp16 tail ----------------
__global__ __launch_bounds__(256, 1) void dec_fused_kernel(
    const int* __restrict__ trg, const float* __restrict__ dec_emb,
    const float* __restrict__ WhP, const float* __restrict__ attn_v,
    const float* __restrict__ enc_proj, const float* __restrict__ enc_outs,
    const float* __restrict__ dWihP, const float* __restrict__ dWhhP,
    const float* __restrict__ bih, const float* __restrict__ bhh,
    const float* __restrict__ h_enc, const float* __restrict__ fcP,
    const float* __restrict__ enc_fc_b,
    float* __restrict__ dec_h, float* __restrict__ xbuf, float* __restrict__ fc_in,
    __half* __restrict__ Ah, unsigned* bar)
{
    const int blk = blockIdx.x, tid = threadIdx.x;
    __shared__ float4 hsh4[64], hc4[128], ctx[2][128];
    __shared__ float hW[256], vsh[256], sc[64], av[64];
    __shared__ float4 xs4[8][160], hs2_4[8][64];
    unsigned tgt = 64;

    const float4* Wh4 = (const float4*)WhP;
    const float4* fc4 = (const float4*)fcP;
    const float4* dWi4 = (const float4*)dWihP;
    const float4* dWh4 = (const float4*)dWhhP;
    float4* dec_h4 = (float4*)dec_h;
    float4* xbuf4 = (float4*)xbuf;
    const float4* eo4 = (const float4*)enc_outs;

    vsh[tid] = attn_v[tid];

    // phase0: hidden = tanh(concat(h_f, h_b) @ enc_fc_W.T + b)
    {
        const float4* he4 = (const float4*)h_enc;
        if (tid < 64) {
            hc4[tid] = he4[0 * 4096 + blk * 64 + tid];
            hc4[64 + tid] = he4[2 * 4096 + blk * 64 + tid];
        }
        __syncthreads();
        float acc = enc_fc_b[tid];
#pragma unroll 8
        for (int e4 = 0; e4 < 128; e4++) {
            float4 w = fc4[e4 * 256 + tid];
            DOT4(acc, hc4[e4], w);
        }
        dec_h[blk * 256 + tid] = tanhf(acc);
    }
    grid_bar(bar, tgt); tgt += 64;

    const int bl = tid >> 5, jl = tid & 31;
    for (int t = 0; t < 63; t++) {
        // ---- phase A: attention + context + embed (b = blk) ----
        {
            const int b = blk;
            if (tid < 64)
                hsh4[tid] = __ldcg(&dec_h4[(t & 1) * 4096 + b * 64 + tid]);
            __syncthreads();
            float acc = 0.f;
#pragma unroll 8
            for (int e4 = 0; e4 < 64; e4++) {
                float4 w = Wh4[e4 * 256 + tid];
                DOT4(acc, hsh4[e4], w);
            }
            hW[tid] = acc;
            __syncthreads();
            {
                int s = tid >> 2, q = tid & 3;
                const float* ep = enc_proj + ((size_t)s * 64 + b) * 256 + q * 64;
                float p = 0.f;
#pragma unroll 8
                for (int jj = 0; jj < 64; jj++)
                    p += vsh[q * 64 + jj] * tanh_fast(ep[jj] + hW[q * 64 + jj]);
                p += __shfl_down_sync(0xffffffffu, p, 2, 4);
                p += __shfl_down_sync(0xffffffffu, p, 1, 4);
                if (q == 0) sc[s] = p;
            }
            __syncthreads();
            if (tid == 0) {
                float mx = sc[0];
                for (int s = 1; s < 64; s++) mx = fmaxf(mx, sc[s]);
                float sum = 0.f;
                for (int s = 0; s < 64; s++) { float e = __expf(sc[s] - mx); av[s] = e; sum += e; }
                float inv = 1.f / sum;
                for (int s = 0; s < 64; s++) av[s] *= inv;
            }
            __syncthreads();
            // context: 512 floats = 128 float4, split s-range over 2 halves
            {
                int e4 = tid & 127, half = tid >> 7;
                float4 w = {0.f, 0.f, 0.f, 0.f};
#pragma unroll 8
                for (int s0 = 0; s0 < 32; s0++) {
                    int s = half * 32 + s0;
                    float a = av[s];
                    float4 v = __ldcg(&eo4[((size_t)s * 64 + b) * 128 + e4]);
                    w.x += a * v.x; w.y += a * v.y; w.z += a * v.z; w.w += a * v.w;
                }
                ctx[half][e4] = w;
            }
            __syncthreads();
            float4* fcrow4 = (float4*)(fc_in + ((size_t)t * 64 + b) * 896);
            if (tid < 128) {
                float4 c0 = ctx[0][tid], c1 = ctx[1][tid];
                float4 w = {c0.x + c1.x, c0.y + c1.y, c0.z + c1.z, c0.w + c1.w};
                xbuf4[b * 160 + 32 + tid] = w;
                fcrow4[64 + tid] = w;
            }
            if (tid < 128) {
                int tok = trg[t * 64 + b];
                float v = dec_emb[(size_t)tok * 128 + tid];
                ((float*)xbuf)[b * 640 + tid] = v;
                ((float*)fcrow4)[768 + tid] = v;
            }
        }
        grid_bar(bar, tgt); tgt += 64;

        // ---- phase B: GRU cell (jg = blk&7, bg = blk>>3) ----
        {
            const int jg = blk & 7, bg = blk >> 3;
            const int b = bg * 8 + bl, j = jg * 32 + jl;
            for (int i = tid; i < 1280; i += 256) {
                int lb = i / 160, e4 = i - lb * 160;
                xs4[lb][e4] = __ldcg(&xbuf4[(bg * 8 + lb) * 160 + e4]);
            }
            for (int i = tid; i < 512; i += 256)
                hs2_4[i >> 6][i & 63] =
                    __ldcg(&dec_h4[(t & 1) * 4096 + (bg * 8 + (i >> 6)) * 64 + (i & 63)]);
            __syncthreads();

            float g0 = bih[j], g1 = bih[256 + j], g2 = bih[512 + j];
#pragma unroll 8
            for (int e4 = 0; e4 < 160; e4++) {
                float4 xv = xs4[bl][e4];
                float4 w0 = dWi4[e4 * 768 + j];
                float4 w1 = dWi4[e4 * 768 + 256 + j];
                float4 w2 = dWi4[e4 * 768 + 512 + j];
                DOT4(g0, xv, w0); DOT4(g1, xv, w1); DOT4(g2, xv, w2);
            }
            float u0 = bhh[j], u1 = bhh[256 + j], u2 = bhh[512 + j];
#pragma unroll 8
            for (int e4 = 0; e4 < 64; e4++) {
                float4 hv = hs2_4[bl][e4];
                float4 w0 = dWh4[e4 * 768 + j];
                float4 w1 = dWh4[e4 * 768 + 256 + j];
                float4 w2 = dWh4[e4 * 768 + 512 + j];
                DOT4(u0, hv, w0); DOT4(u1, hv, w1); DOT4(u2, hv, w2);
            }
            float r = sigmoidf_(g0 + u0);
            float z = sigmoidf_(g1 + u1);
            float n = tanhf(g2 + r * u2);
            float h2 = (1.f - z) * n + z * ((const float*)hs2_4)[bl * 256 + j];
            dec_h[((t + 1) & 1) * 16384 + b * 256 + j] = h2;
            fc_in[((size_t)t * 64 + b) * 896 + j] = h2;
        }
        grid_bar(bar, tgt); tgt += 64;
    }

    // tail: fc_in -> fp16 (vectorized; rows [4032,4096) zero-padded)
    {
        const float4* fi4 = (const float4*)fc_in;
        uint2* Ah2 = (uint2*)Ah;
        for (long i4 = blk * 256 + tid; i4 < 917504; i4 += 16384) {
            float4 x = (i4 < 903168) ? __ldcg(&fi4[i4]) : make_float4(0.f, 0.f, 0.f, 0.f);
            __half2 lo = __floats2half2_rn(x.x, x.y);
            __half2 hi = __floats2half2_rn(x.z, x.w);
            Ah2[i4] = make_uint2(*(uint32_t*)&lo, *(uint32_t*)&hi);
        }
    }
}

// ---------------- fc GEMM: fp16, fp32 accum, 4-stage cp.async pipeline ----------------
#define FC_STAGE 20480

__device__ __forceinline__ void fc_load_stage(
    uint32_t sb, int tid, int m0, int n0, int k0,
    const __half* __restrict__ Ah, const __half* __restrict__ Bh)
{
#pragma unroll
    for (int i = 0; i < 2; i++) {
        int v = tid + 256 * i;
        int r = v >> 2, c = v & 3;
        uint32_t so = (uint32_t)(r * 80 + c * 16);
        CP_ASYNC16(sb + so, Ah + (size_t)(m0 + r) * 896 + k0 + c * 8);
        CP_ASYNC16(sb + 10240 + so, Bh + (size_t)(n0 + r) * 896 + k0 + c * 8);
    }
    CP_ASYNC_COMMIT();
}

__global__ __launch_bounds__(256, 2)
void fc_mma_kernel(const __half* __restrict__ Ah, const __half* __restrict__ Bh,
                   const float* __restrict__ bias, float* __restrict__ C)
{
    extern __shared__ __align__(16) char raw_smem[];
    const int tid = threadIdx.x, lane = tid & 31, wid = tid >> 5;
    const int wm = wid & 3, wn = wid >> 2;
    const int m0 = blockIdx.x * 128;
    const int n0 = blockIdx.y * 128;
    const uint32_t sbase = smem_u32(raw_smem);

    float acc[2][8][4];
#pragma unroll
    for (int i = 0; i < 2; i++)
#pragma unroll
        for (int j = 0; j < 8; j++)
#pragma unroll
            for (int q = 0; q < 4; q++) acc[i][j][q] = 0.f;

    fc_load_stage(sbase + 0 * FC_STAGE, tid, m0, n0, 0, Ah, Bh);
    fc_load_stage(sbase + 1 * FC_STAGE, tid, m0, n0, 32, Ah, Bh);
    fc_load_stage(sbase + 2 * FC_STAGE, tid, m0, n0, 64, Ah, Bh);

    const uint32_t a_off = (uint32_t)((wm * 32 + (lane & 15)) * 80 + (lane >> 4) * 16);
    const uint32_t b_off = (uint32_t)(10240 +
        (wn * 64 + (lane & 7) + ((lane >> 4) << 3)) * 80 + ((lane >> 3) & 1) * 16);

#pragma unroll 1
    for (int s = 0; s < 28; s++) {
        const uint32_t base = sbase + (uint32_t)(s & 3) * FC_STAGE;
        CP_ASYNC_WAIT2();
        __syncthreads();
        if (s + 3 < 28)
            fc_load_stage(sbase + (uint32_t)((s + 3) & 3) * FC_STAGE, tid, m0, n0,
                          (s + 3) * 32, Ah, Bh);
        else
            CP_ASYNC_COMMIT();

#pragma unroll
        for (int ks = 0; ks < 2; ks++) {
            uint32_t a[2][4];
#pragma unroll
            for (int i = 0; i < 2; i++)
                LDSM_X4(a[i], base + a_off + (uint32_t)(i * 16 * 80 + ks * 32));
#pragma unroll
            for (int jp = 0; jp < 4; jp++) {
                uint32_t b4[4];
                LDSM_X4(b4, base + b_off + (uint32_t)(jp * 16 * 80 + ks * 32));
#pragma unroll
                for (int i = 0; i < 2; i++) {
                    MMA_F16(acc[i][jp * 2 + 0], a[i], b4 + 0);
                    MMA_F16(acc[i][jp * 2 + 1], a[i], b4 + 2);
                }
            }
        }
    }

    const int row0 = m0 + wm * 32 + (lane >> 2);
    const int col0 = n0 + wn * 64 + (lane & 3) * 2;
#pragma unroll
    for (int i = 0; i < 2; i++) {
#pragma unroll
        for (int j = 0; j < 8; j++) {
            int c = col0 + j * 8;
            float b0 = bias[c], b1 = bias[c + 1];
            int r = row0 + i * 16;
            if (r < 4032) {
                float2 o = {acc[i][j][0] + b0, acc[i][j][1] + b1};
                *(float2*)(C + (size_t)r * 32000 + c) = o;
            }
            if (r + 8 < 4032) {
                float2 o = {acc[i][j][2] + b0, acc[i][j][3] + b1};
                *(float2*)(C + (size_t)(r + 8) * 32000 + c) = o;
            }
        }
    }
}

// ---------------- host ----------------
extern "C" void kernel_launch(void* const* d_in, const int* in_sizes, int n_in,
                              void* d_out, int out_size) {
    (void)in_sizes; (void)n_in; (void)out_size;
    const int*   src       = (const int*)d_in[0];
    const int*   trg       = (const int*)d_in[1];
    const float* enc_emb   = (const float*)d_in[2];
    const float* enc_Wih_f = (const float*)d_in[3];
    const float* enc_Whh_f = (const float*)d_in[4];
    const float* enc_bih_f = (const float*)d_in[5];
    const float* enc_bhh_f = (const float*)d_in[6];
    const float* enc_Wih_b = (const float*)d_in[7];
    const float* enc_Whh_b = (const float*)d_in[8];
    const float* enc_bih_b = (const float*)d_in[9];
    const float* enc_bhh_b = (const float*)d_in[10];
    const float* enc_fc_W  = (const float*)d_in[11];
    const float* enc_fc_b  = (const float*)d_in[12];
    const float* attn_W    = (const float*)d_in[13];
    const float* attn_b    = (const float*)d_in[14];
    const float* attn_v    = (const float*)d_in[15];
    const float* dec_emb   = (const float*)d_in[16];
    const float* dec_Wih   = (const float*)d_in[17];
    const float* dec_Whh   = (const float*)d_in[18];
    const float* dec_bih   = (const float*)d_in[19];
    const float* dec_bhh   = (const float*)d_in[20];
    const float* fc_W      = (const float*)d_in[21];
    const float* fc_b      = (const float*)d_in[22];
    float* out = (float*)d_out;

    float* base = nullptr;   cudaGetSymbolAddress((void**)&base, g_scratch);
    __half* hb = nullptr;    cudaGetSymbolAddress((void**)&hb, g_h);
    unsigned* bar = nullptr; cudaGetSymbolAddress((void**)&bar, g_bar);

    size_t off = 0;
    auto carve = [&](size_t n) { float* p = base + off; off += n; return p; };
    float* emb      = carve((size_t)4096 * 128);
    float* gi_f     = carve((size_t)4096 * 768);
    float* gi_b     = carve((size_t)4096 * 768);
    float* h_enc    = carve((size_t)4 * 64 * 256);
    float* enc_outs = carve((size_t)4096 * 512);
    float* enc_proj = carve((size_t)4096 * 256);
    float* dec_h    = carve((size_t)2 * 64 * 256);
    float* xbuf     = carve((size_t)64 * 640);
    float* fc_in    = carve((size_t)4032 * 896);
    float* WhhP_f   = carve((size_t)64 * 3072);
    float* WhhP_b   = carve((size_t)64 * 3072);
    float* dWhhP    = carve((size_t)64 * 3072);
    float* dWihP    = carve((size_t)160 * 3072);
    float* WhP      = carve((size_t)64 * 1024);
    float* fcP      = carve((size_t)128 * 1024);
    float* WeP      = carve((size_t)128 * 1024);
    __half* Bh = hb;
    __half* Ah = hb + 28672000;

    cudaMemsetAsync(bar, 0, 4 * sizeof(unsigned));

    // (a) zero row-0 of outputs
    zero_out_kernel<<<8000, 256>>>(out);
    // (b) prologue: fc_W->fp16, embed, pack4 weight transposes
    prologue_kernel<<<119552, 256>>>(fc_W, Bh, src, enc_emb, emb,
                                     enc_Whh_f, WhhP_f, enc_Whh_b, WhhP_b,
                                     dec_Whh, dWhhP, dec_Wih, dWihP,
                                     attn_W, WhP, enc_fc_W, fcP, WeP);
    // (c) both input-gate GEMMs
    sgemm_gi_kernel<<<dim3(6, 64, 2), 256>>>(emb, enc_Wih_f, enc_Wih_b,
                                             enc_bih_f, enc_bih_b, gi_f, gi_b);
    // (d) persistent encoder (+enc_proj tail)
    enc_fused_kernel<<<128, 256>>>(WhhP_f, WhhP_b, enc_bhh_f, enc_bhh_b,
                                   gi_f, gi_b, h_enc, enc_outs,
                                   WeP, attn_b, enc_proj, bar);
    // (e) persistent decoder (+enc_fc init, +fp16 convert tail)
    dec_fused_kernel<<<64, 256>>>(trg, dec_emb, WhP, attn_v, enc_proj, enc_outs,
                                  dWihP, dWhhP, dec_bih, dec_bhh, h_enc, fcP, enc_fc_b,
                                  dec_h, xbuf, fc_in, Ah, bar + 3);
    // (f) fc: fp16 tensor-core GEMM, 4-stage pipeline
    cudaFuncSetAttribute(fc_mma_kernel, cudaFuncAttributeMaxDynamicSharedMemorySize,
                         4 * FC_STAGE);
    fc_mma_kernel<<<dim3(32, 250), 256, 4 * FC_STAGE>>>(Ah, Bh, fc_b,
                                                        out + (size_t)64 * 32000);
}

// round 17
// speedup vs baseline: 1.0021x; 1.0021x over previous
#include <cuda_runtime.h>
#include <cuda_fp16.h>
#include <cstdint>

// V=32000, S=64, T=64, B=64, E=128, EH=256, DH=256
__device__ float g_scratch[15200000];
__device__ __half g_h[32400000];     // Bh[28672000], Ah[3670016]
__device__ unsigned g_bar[4];        // enc dir0, enc dir1, enc final, dec

__device__ __forceinline__ float sigmoidf_(float x) { return 1.0f / (1.0f + __expf(-x)); }
__device__ __forceinline__ float tanh_fast(float x) {
    float y; asm("tanh.approx.f32 %0, %1;" : "=f"(y) : "f"(x)); return y;
}
__device__ __forceinline__ uint32_t smem_u32(const void* p) {
    uint32_t a;
    asm("{ .reg .u64 t; cvta.to.shared.u64 t, %1; cvt.u32.u64 %0, t; }" : "=r"(a) : "l"(p));
    return a;
}
#define CP_ASYNC16(dst, src) \
    asm volatile("cp.async.cg.shared.global [%0], [%1], 16;" :: "r"(dst), "l"(src) : "memory")
#define CP_ASYNC_COMMIT() asm volatile("cp.async.commit_group;" ::: "memory")
#define CP_ASYNC_WAIT2()  asm volatile("cp.async.wait_group 2;" ::: "memory")
#define LDSM_X4(r, addr) \
    asm volatile("ldmatrix.sync.aligned.m8n8.x4.shared.b16 {%0,%1,%2,%3}, [%4];" \
        : "=r"((r)[0]), "=r"((r)[1]), "=r"((r)[2]), "=r"((r)[3]) : "r"(addr))
#define MMA_F16(c, a, b) \
    asm volatile("mma.sync.aligned.m16n8k16.row.col.f32.f16.f16.f32 " \
        "{%0,%1,%2,%3}, {%4,%5,%6,%7}, {%8,%9}, {%0,%1,%2,%3};" \
        : "+f"((c)[0]), "+f"((c)[1]), "+f"((c)[2]), "+f"((c)[3]) \
        : "r"((a)[0]), "r"((a)[1]), "r"((a)[2]), "r"((a)[3]), "r"((b)[0]), "r"((b)[1]))

// NOTE: parameter names must not collide with float4 field names (.x/.y/.z/.w)
#define DOT4(acc, v_, w_) \
    (acc) += (v_).x*(w_).x + (v_).y*(w_).y + (v_).z*(w_).z + (v_).w*(w_).w

// grid-wide barrier (monotonic counter; reset each replay by memset node)
__device__ __forceinline__ void grid_bar(unsigned* cnt, unsigned target) {
    __syncthreads();
    if (threadIdx.x == 0) {
        asm volatile("red.release.gpu.global.add.u32 [%0], %1;" :: "l"(cnt), "r"(1u) : "memory");
        unsigned v;
        do {
            asm volatile("ld.acquire.gpu.global.u32 %0, [%1];" : "=r"(v) : "l"(cnt) : "memory");
            if (v < target) __nanosleep(64);
        } while (v < target);
    }
    __syncthreads();
}

__global__ void zero_out_kernel(float* __restrict__ p) {
    p[blockIdx.x * 256 + threadIdx.x] = 0.f;
}

// ---------------- prologue: pack4 transposes + embed + fc_W->fp16 ----------------
// P[(e>>2)*(ncol*4) + col*4 + (e&3)] = src[col*ld + off + e]
__device__ __forceinline__ void pack4_job(const float* __restrict__ src, float* __restrict__ dst,
                                          int ncol, int ne, int ld, int off, int blk, int tid) {
    int idx = blk * 256 + tid;
    if (idx >= ncol * ne) return;
    int col = idx / ne, e = idx - col * ne;
    dst[(e >> 2) * (ncol * 4) + col * 4 + (e & 3)] = src[(size_t)col * ld + off + e];
}

__global__ void prologue_kernel(
    const float* __restrict__ fc_W, __half* __restrict__ Bh,
    const int* __restrict__ src, const float* __restrict__ enc_emb, float* __restrict__ emb,
    const float* __restrict__ enc_Whh_f, float* __restrict__ WhhP_f,
    const float* __restrict__ enc_Whh_b, float* __restrict__ WhhP_b,
    const float* __restrict__ dec_Whh, float* __restrict__ dWhhP,
    const float* __restrict__ dec_Wih, float* __restrict__ dWihP,
    const float* __restrict__ attn_W, float* __restrict__ WhP,
    const float* __restrict__ enc_fc_W, float* __restrict__ fcP,
    float* __restrict__ WeP)
{
    int blk = blockIdx.x, tid = threadIdx.x;
    if (blk < 112000) {
        long i = (long)blk * 256 + tid;
        Bh[i] = __float2half(fc_W[i]);
        return;
    }
    blk -= 112000;
    if (blk < 2048) {
        int e = blk * 256 + tid;
        int sb = e >> 7, c = e & 127;
        emb[e] = enc_emb[(size_t)src[sb] * 128 + c];
        return;
    }
    blk -= 2048;
    if (blk < 768)  { pack4_job(enc_Whh_f, WhhP_f, 768, 256, 256, 0, blk, tid); return; } blk -= 768;
    if (blk < 768)  { pack4_job(enc_Whh_b, WhhP_b, 768, 256, 256, 0, blk, tid); return; } blk -= 768;
    if (blk < 768)  { pack4_job(dec_Whh,  dWhhP,  768, 256, 256, 0, blk, tid); return; } blk -= 768;
    if (blk < 1920) { pack4_job(dec_Wih,  dWihP,  768, 640, 640, 0, blk, tid); return; } blk -= 1920;
    if (blk < 256)  { pack4_job(attn_W,   WhP,    256, 256, 768, 0, blk, tid); return; } blk -= 256;
    if (blk < 512)  { pack4_job(enc_fc_W, fcP,    256, 512, 512, 0, blk, tid); return; } blk -= 512;
    pack4_job(attn_W, WeP, 256, 512, 768, 256, blk, tid);   // W_e
}

// ---------------- fp32 sgemm (both encoder input-gate GEMMs) ----------------
__device__ __forceinline__ void sgemm_body(
    int M, int N, int K,
    const float* __restrict__ A, int lda,
    const float* __restrict__ Bm, int ldb,
    const float* __restrict__ bias, float* __restrict__ C, int ldc,
    float As[8][64], float Bs[8][128])
{
    const int tid = threadIdx.x;
    const int m0 = blockIdx.y * 64, n0 = blockIdx.x * 128;
    const int tx = tid & 15, ty = tid >> 4;
    const int ar = tid >> 2, ac = tid & 3;
    const int br = tid >> 1, bc = tid & 1;
    const float* Ap = A + (size_t)(m0 + ar) * lda + ac * 2;
    const float* Bp = Bm + (size_t)(n0 + br) * ldb + bc * 4;

    float acc[4][8];
#pragma unroll
    for (int i = 0; i < 4; i++)
#pragma unroll
        for (int j = 0; j < 8; j++) acc[i][j] = 0.f;

    for (int k0 = 0; k0 < K; k0 += 8) {
        float2 av = *(const float2*)(Ap + k0);
        float4 bv = *(const float4*)(Bp + k0);
        As[ac * 2 + 0][ar] = av.x; As[ac * 2 + 1][ar] = av.y;
        Bs[bc * 4 + 0][br] = bv.x; Bs[bc * 4 + 1][br] = bv.y;
        Bs[bc * 4 + 2][br] = bv.z; Bs[bc * 4 + 3][br] = bv.w;
        __syncthreads();
#pragma unroll
        for (int k = 0; k < 8; k++) {
            float a[4], bb[8];
            *(float4*)a = *(const float4*)&As[k][ty * 4];
            *(float4*)(bb + 0) = *(const float4*)&Bs[k][tx * 8 + 0];
            *(float4*)(bb + 4) = *(const float4*)&Bs[k][tx * 8 + 4];
#pragma unroll
            for (int i = 0; i < 4; i++)
#pragma unroll
                for (int j = 0; j < 8; j++) acc[i][j] += a[i] * bb[j];
        }
        __syncthreads();
    }
    const float* bp = bias + n0 + tx * 8;
#pragma unroll
    for (int i = 0; i < 4; i++) {
        float* cp = C + (size_t)(m0 + ty * 4 + i) * ldc + n0 + tx * 8;
#pragma unroll
        for (int q = 0; q < 8; q++) cp[q] = acc[i][q] + bp[q];
    }
}

__global__ __launch_bounds__(256) void sgemm_gi_kernel(
    const float* A, const float* W0, const float* W1,
    const float* b0, const float* b1, float* C0, float* C1)
{
    __shared__ float As[8][64], Bs[8][128];
    if (blockIdx.z == 0) sgemm_body(4096, 768, 128, A, 128, W0, 128, b0, C0, 768, As, Bs);
    else                 sgemm_body(4096, 768, 128, A, 128, W1, 128, b1, C1, 768, As, Bs);
}

// ---------------- persistent encoder: 64 steps both dirs + enc_proj tail ----------------
__global__ __launch_bounds__(256, 1) void enc_fused_kernel(
    const float* __restrict__ WhhP_f, const float* __restrict__ WhhP_b,
    const float* __restrict__ bhh_f, const float* __restrict__ bhh_b,
    const float* __restrict__ gi_f, const float* __restrict__ gi_b,
    float* __restrict__ h_enc, float* __restrict__ enc_outs,
    const float* __restrict__ WeP, const float* __restrict__ attn_b,
    float* __restrict__ enc_proj, unsigned* bar)
{
    const int blk = blockIdx.x, tid = threadIdx.x;
    const int dir = blk >> 6, rest = blk & 63, jg = rest & 7, bg = rest >> 3;
    const int bl = tid >> 5, jl = tid & 31;
    const int b = bg * 8 + bl, j = jg * 32 + jl;
    const float4* Wp4 = (const float4*)(dir ? WhhP_b : WhhP_f);
    const float* bhh = dir ? bhh_b : bhh_f;
    const float* gibase = dir ? gi_b : gi_f;
    __shared__ float4 hs4[8][64];
    __shared__ float4 shp4[16][128];

    unsigned* dbar = bar + dir;
    h_enc[(dir * 2 + 0) * 16384 + b * 256 + j] = 0.f;
    unsigned tgt = 64;
    grid_bar(dbar, tgt); tgt += 64;

    const float bh0 = bhh[j], bh1 = bhh[256 + j], bh2 = bhh[512 + j];

    for (int t = 0; t < 64; t++) {
        const float4* hprev4 = (const float4*)(h_enc + (dir * 2 + (t & 1)) * 16384);
        for (int i = tid; i < 512; i += 256)
            hs4[i >> 6][i & 63] = __ldcg(&hprev4[(bg * 8 + (i >> 6)) * 64 + (i & 63)]);
        __syncthreads();

        float a0 = bh0, a1 = bh1, a2 = bh2;
#pragma unroll 8
        for (int e4 = 0; e4 < 64; e4++) {
            float4 h = hs4[bl][e4];
            float4 w0 = Wp4[e4 * 768 + j];
            float4 w1 = Wp4[e4 * 768 + 256 + j];
            float4 w2 = Wp4[e4 * 768 + 512 + j];
            DOT4(a0, h, w0); DOT4(a1, h, w1); DOT4(a2, h, w2);
        }
        int tt = dir ? (63 - t) : t;
        const float* gi = gibase + ((size_t)tt * 64 + b) * 768;
        float r = sigmoidf_(gi[j] + a0);
        float z = sigmoidf_(gi[256 + j] + a1);
        float n = tanhf(gi[512 + j] + r * a2);
        float h2 = (1.f - z) * n + z * ((const float*)hs4)[bl * 256 + j];
        h_enc[(dir * 2 + ((t + 1) & 1)) * 16384 + b * 256 + j] = h2;
        enc_outs[((size_t)tt * 64 + b) * 512 + dir * 256 + j] = h2;
        grid_bar(dbar, tgt); tgt += 64;
    }

    // both dirs must finish before the enc_proj tail reads enc_outs
    grid_bar(bar + 2, 128);

    // tail: enc_proj[r, c] = enc_outs[r,:] @ W_e[c,:] + attn_b[c]; 32 rows/block
    const float4* eo4 = (const float4*)enc_outs;
    const float4* We4 = (const float4*)WeP;
    const float ab = attn_b[tid];
    for (int chunk = 0; chunk < 2; chunk++) {
        int r0 = blk * 32 + chunk * 16;
        for (int i = tid; i < 2048; i += 256)
            shp4[i >> 7][i & 127] = __ldcg(&eo4[(size_t)(r0 + (i >> 7)) * 128 + (i & 127)]);
        __syncthreads();
        float a16[16];
#pragma unroll
        for (int q = 0; q < 16; q++) a16[q] = ab;
#pragma unroll 4
        for (int e4 = 0; e4 < 128; e4++) {
            float4 w = We4[e4 * 256 + tid];
#pragma unroll
            for (int q = 0; q < 16; q++) DOT4(a16[q], shp4[q][e4], w);
        }
#pragma unroll
        for (int q = 0; q < 16; q++)
            enc_proj[(size_t)(r0 + q) * 256 + tid] = a16[q];
        __syncthreads();
    }
}

// ---------------- persistent decoder: enc_fc init + 63 steps + fp16 tail ----------------
__global__ __launch_bounds__(256, 1) void dec_fused_kernel(
    const int* __restrict__ trg, const float* __restrict__ dec_emb,
    const float* __restrict__ WhP, const float* __restrict__ attn_v,
    const float* __restrict__ enc_proj, const float* __restrict__ enc_outs,
    const float* __restrict__ dWihP, const float* __restrict__ dWhhP,
    const float* __restrict__ bih, const float* __restrict__ bhh,
    const float* __restrict__ h_enc, const float* __restrict__ fcP,
    const float* __restrict__ enc_fc_b,
    float* __restrict__ dec_h, float* __restrict__ xbuf, float* __restrict__ fc_in,
    __half* __restrict__ Ah, unsigned* bar)
{
    const int blk = blockIdx.x, tid = threadIdx.x;
    __shared__ float4 hsh4[64], hc4[128], ctx[2][128];
    __shared__ float hW[256], vsh[256], sc[64], av[64];
    __shared__ float4 xs4[8][160], hs2_4[8][64];
    unsigned tgt = 64;

    const float4* Wh4 = (const float4*)WhP;
    const float4* fc4 = (const float4*)fcP;
    const float4* dWi4 = (const float4*)dWihP;
    const float4* dWh4 = (const float4*)dWhhP;
    float4* dec_h4 = (float4*)dec_h;
    float4* xbuf4 = (float4*)xbuf;
    const float4* eo4 = (const float4*)enc_outs;

    vsh[tid] = attn_v[tid];

    // phase0: hidden = tanh(concat(h_f, h_b) @ enc_fc_W.T + b)
    {
        const float4* he4 = (const float4*)h_enc;
        if (tid < 64) {
            hc4[tid] = he4[0 * 4096 + blk * 64 + tid];
            hc4[64 + tid] = he4[2 * 4096 + blk * 64 + tid];
        }
        __syncthreads();
        float acc = enc_fc_b[tid];
#pragma unroll 8
        for (int e4 = 0; e4 < 128; e4++) {
            float4 w = fc4[e4 * 256 + tid];
            DOT4(acc, hc4[e4], w);
        }
        dec_h[blk * 256 + tid] = tanhf(acc);
    }
    grid_bar(bar, tgt); tgt += 64;

    const int bl = tid >> 5, jl = tid & 31;
    for (int t = 0; t < 63; t++) {
        // ---- phase A: attention + context + embed (b = blk) ----
        {
            const int b = blk;
            if (tid < 64)
                hsh4[tid] = __ldcg(&dec_h4[(t & 1) * 4096 + b * 64 + tid]);
            __syncthreads();
            float acc = 0.f;
#pragma unroll 8
            for (int e4 = 0; e4 < 64; e4++) {
                float4 w = Wh4[e4 * 256 + tid];
                DOT4(acc, hsh4[e4], w);
            }
            hW[tid] = acc;
            __syncthreads();
            {
                int s = tid >> 2, q = tid & 3;
                const float* ep = enc_proj + ((size_t)s * 64 + b) * 256 + q * 64;
                float p = 0.f;
#pragma unroll 8
                for (int jj = 0; jj < 64; jj++)
                    p += vsh[q * 64 + jj] * tanh_fast(ep[jj] + hW[q * 64 + jj]);
                p += __shfl_down_sync(0xffffffffu, p, 2, 4);
                p += __shfl_down_sync(0xffffffffu, p, 1, 4);
                if (q == 0) sc[s] = p;
            }
            __syncthreads();
            if (tid == 0) {
                float mx = sc[0];
                for (int s = 1; s < 64; s++) mx = fmaxf(mx, sc[s]);
                float sum = 0.f;
                for (int s = 0; s < 64; s++) { float e = __expf(sc[s] - mx); av[s] = e; sum += e; }
                float inv = 1.f / sum;
                for (int s = 0; s < 64; s++) av[s] *= inv;
            }
            __syncthreads();
            // context: 512 floats = 128 float4, split s-range over 2 halves
            {
                int e4 = tid & 127, half = tid >> 7;
                float4 w = {0.f, 0.f, 0.f, 0.f};
#pragma unroll 8
                for (int s0 = 0; s0 < 32; s0++) {
                    int s = half * 32 + s0;
                    float a = av[s];
                    float4 v = __ldcg(&eo4[((size_t)s * 64 + b) * 128 + e4]);
                    w.x += a * v.x; w.y += a * v.y; w.z += a * v.z; w.w += a * v.w;
                }
                ctx[half][e4] = w;
            }
            __syncthreads();
            float4* fcrow4 = (float4*)(fc_in + ((size_t)t * 64 + b) * 896);
            if (tid < 128) {
                float4 c0 = ctx[0][tid], c1 = ctx[1][tid];
                float4 w = {c0.x + c1.x, c0.y + c1.y, c0.z + c1.z, c0.w + c1.w};
                xbuf4[b * 160 + 32 + tid] = w;
                fcrow4[64 + tid] = w;
            }
            if (tid < 128) {
                int tok = trg[t * 64 + b];
                float v = dec_emb[(size_t)tok * 128 + tid];
                ((float*)xbuf)[b * 640 + tid] = v;
                ((float*)fcrow4)[768 + tid] = v;
            }
        }
        grid_bar(bar, tgt); tgt += 64;

        // ---- phase B: GRU cell (jg = blk&7, bg = blk>>3) ----
        {
            const int jg = blk & 7, bg = blk >> 3;
            const int b = bg * 8 + bl, j = jg * 32 + jl;
            for (int i = tid; i < 1280; i += 256) {
                int lb = i / 160, e4 = i - lb * 160;
                xs4[lb][e4] = __ldcg(&xbuf4[(bg * 8 + lb) * 160 + e4]);
            }
            for (int i = tid; i < 512; i += 256)
                hs2_4[i >> 6][i & 63] =
                    __ldcg(&dec_h4[(t & 1) * 4096 + (bg * 8 + (i >> 6)) * 64 + (i & 63)]);
            __syncthreads();

            float g0 = bih[j], g1 = bih[256 + j], g2 = bih[512 + j];
#pragma unroll 8
            for (int e4 = 0; e4 < 160; e4++) {
                float4 xv = xs4[bl][e4];
                float4 w0 = dWi4[e4 * 768 + j];
                float4 w1 = dWi4[e4 * 768 + 256 + j];
                float4 w2 = dWi4[e4 * 768 + 512 + j];
                DOT4(g0, xv, w0); DOT4(g1, xv, w1); DOT4(g2, xv, w2);
            }
            float u0 = bhh[j], u1 = bhh[256 + j], u2 = bhh[512 + j];
#pragma unroll 8
            for (int e4 = 0; e4 < 64; e4++) {
                float4 hv = hs2_4[bl][e4];
                float4 w0 = dWh4[e4 * 768 + j];
                float4 w1 = dWh4[e4 * 768 + 256 + j];
                float4 w2 = dWh4[e4 * 768 + 512 + j];
                DOT4(u0, hv, w0); DOT4(u1, hv, w1); DOT4(u2, hv, w2);
            }
            float r = sigmoidf_(g0 + u0);
            float z = sigmoidf_(g1 + u1);
            float n = tanhf(g2 + r * u2);
            float h2 = (1.f - z) * n + z * ((const float*)hs2_4)[bl * 256 + j];
            dec_h[((t + 1) & 1) * 16384 + b * 256 + j] = h2;
            fc_in[((size_t)t * 64 + b) * 896 + j] = h2;
        }
        grid_bar(bar, tgt); tgt += 64;
    }

    // tail: fc_in -> fp16 (vectorized; rows [4032,4096) zero-padded)
    {
        const float4* fi4 = (const float4*)fc_in;
        uint2* Ah2 = (uint2*)Ah;
        for (long i4 = blk * 256 + tid; i4 < 917504; i4 += 16384) {
            float4 x = (i4 < 903168) ? __ldcg(&fi4[i4]) : make_float4(0.f, 0.f, 0.f, 0.f);
            __half2 lo = __floats2half2_rn(x.x, x.y);
            __half2 hi = __floats2half2_rn(x.z, x.w);
            Ah2[i4] = make_uint2(*(uint32_t*)&lo, *(uint32_t*)&hi);
        }
    }
}

// ---------------- fc GEMM: fp16, fp32 accum, 4-stage cp.async pipeline ----------------
#define FC_STAGE 20480

__device__ __forceinline__ void fc_load_stage(
    uint32_t sb, int tid, int m0, int n0, int k0,
    const __half* __restrict__ Ah, const __half* __restrict__ Bh)
{
#pragma unroll
    for (int i = 0; i < 2; i++) {
        int v = tid + 256 * i;
        int r = v >> 2, c = v & 3;
        uint32_t so = (uint32_t)(r * 80 + c * 16);
        CP_ASYNC16(sb + so, Ah + (size_t)(m0 + r) * 896 + k0 + c * 8);
        CP_ASYNC16(sb + 10240 + so, Bh + (size_t)(n0 + r) * 896 + k0 + c * 8);
    }
    CP_ASYNC_COMMIT();
}

__global__ __launch_bounds__(256, 2)
void fc_mma_kernel(const __half* __restrict__ Ah, const __half* __restrict__ Bh,
                   const float* __restrict__ bias, float* __restrict__ C)
{
    extern __shared__ __align__(16) char raw_smem[];
    const int tid = threadIdx.x, lane = tid & 31, wid = tid >> 5;
    const int wm = wid & 3, wn = wid >> 2;
    const int m0 = blockIdx.x * 128;
    const int n0 = blockIdx.y * 128;
    const uint32_t sbase = smem_u32(raw_smem);

    float acc[2][8][4];
#pragma unroll
    for (int i = 0; i < 2; i++)
#pragma unroll
        for (int j = 0; j < 8; j++)
#pragma unroll
            for (int q = 0; q < 4; q++) acc[i][j][q] = 0.f;

    fc_load_stage(sbase + 0 * FC_STAGE, tid, m0, n0, 0, Ah, Bh);
    fc_load_stage(sbase + 1 * FC_STAGE, tid, m0, n0, 32, Ah, Bh);
    fc_load_stage(sbase + 2 * FC_STAGE, tid, m0, n0, 64, Ah, Bh);

    const uint32_t a_off = (uint32_t)((wm * 32 + (lane & 15)) * 80 + (lane >> 4) * 16);
    const uint32_t b_off = (uint32_t)(10240 +
        (wn * 64 + (lane & 7) + ((lane >> 4) << 3)) * 80 + ((lane >> 3) & 1) * 16);

#pragma unroll 1
    for (int s = 0; s < 28; s++) {
        const uint32_t base = sbase + (uint32_t)(s & 3) * FC_STAGE;
        CP_ASYNC_WAIT2();
        __syncthreads();
        if (s + 3 < 28)
            fc_load_stage(sbase + (uint32_t)((s + 3) & 3) * FC_STAGE, tid, m0, n0,
                          (s + 3) * 32, Ah, Bh);
        else
            CP_ASYNC_COMMIT();

#pragma unroll
        for (int ks = 0; ks < 2; ks++) {
            uint32_t a[2][4];
#pragma unroll
            for (int i = 0; i < 2; i++)
                LDSM_X4(a[i], base + a_off + (uint32_t)(i * 16 * 80 + ks * 32));
#pragma unroll
            for (int jp = 0; jp < 4; jp++) {
                uint32_t b4[4];
                LDSM_X4(b4, base + b_off + (uint32_t)(jp * 16 * 80 + ks * 32));
#pragma unroll
                for (int i = 0; i < 2; i++) {
                    MMA_F16(acc[i][jp * 2 + 0], a[i], b4 + 0);
                    MMA_F16(acc[i][jp * 2 + 1], a[i], b4 + 2);
                }
            }
        }
    }

    const int row0 = m0 + wm * 32 + (lane >> 2);
    const int col0 = n0 + wn * 64 + (lane & 3) * 2;
#pragma unroll
    for (int i = 0; i < 2; i++) {
#pragma unroll
        for (int j = 0; j < 8; j++) {
            int c = col0 + j * 8;
            float b0 = bias[c], b1 = bias[c + 1];
            int r = row0 + i * 16;
            if (r < 4032) {
                float2 o = {acc[i][j][0] + b0, acc[i][j][1] + b1};
                *(float2*)(C + (size_t)r * 32000 + c) = o;
            }
            if (r + 8 < 4032) {
                float2 o = {acc[i][j][2] + b0, acc[i][j][3] + b1};
                *(float2*)(C + (size_t)(r + 8) * 32000 + c) = o;
            }
        }
    }
}

// ---------------- host ----------------
extern "C" void kernel_launch(void* const* d_in, const int* in_sizes, int n_in,
                              void* d_out, int out_size) {
    (void)in_sizes; (void)n_in; (void)out_size;
    const int*   src       = (const int*)d_in[0];
    const int*   trg       = (const int*)d_in[1];
    const float* enc_emb   = (const float*)d_in[2];
    const float* enc_Wih_f = (const float*)d_in[3];
    const float* enc_Whh_f = (const float*)d_in[4];
    const float* enc_bih_f = (const float*)d_in[5];
    const float* enc_bhh_f = (const float*)d_in[6];
    const float* enc_Wih_b = (const float*)d_in[7];
    const float* enc_Whh_b = (const float*)d_in[8];
    const float* enc_bih_b = (const float*)d_in[9];
    const float* enc_bhh_b = (const float*)d_in[10];
    const float* enc_fc_W  = (const float*)d_in[11];
    const float* enc_fc_b  = (const float*)d_in[12];
    const float* attn_W    = (const float*)d_in[13];
    const float* attn_b    = (const float*)d_in[14];
    const float* attn_v    = (const float*)d_in[15];
    const float* dec_emb   = (const float*)d_in[16];
    const float* dec_Wih   = (const float*)d_in[17];
    const float* dec_Whh   = (const float*)d_in[18];
    const float* dec_bih   = (const float*)d_in[19];
    const float* dec_bhh   = (const float*)d_in[20];
    const float* fc_W      = (const float*)d_in[21];
    const float* fc_b      = (const float*)d_in[22];
    float* out = (float*)d_out;

    float* base = nullptr;   cudaGetSymbolAddress((void**)&base, g_scratch);
    __half* hb = nullptr;    cudaGetSymbolAddress((void**)&hb, g_h);
    unsigned* bar = nullptr; cudaGetSymbolAddress((void**)&bar, g_bar);

    size_t off = 0;
    auto carve = [&](size_t n) { float* p = base + off; off += n; return p; };
    float* emb      = carve((size_t)4096 * 128);
    float* gi_f     = carve((size_t)4096 * 768);
    float* gi_b     = carve((size_t)4096 * 768);
    float* h_enc    = carve((size_t)4 * 64 * 256);
    float* enc_outs = carve((size_t)4096 * 512);
    float* enc_proj = carve((size_t)4096 * 256);
    float* dec_h    = carve((size_t)2 * 64 * 256);
    float* xbuf     = carve((size_t)64 * 640);
    float* fc_in    = carve((size_t)4032 * 896);
    float* WhhP_f   = carve((size_t)64 * 3072);
    float* WhhP_b   = carve((size_t)64 * 3072);
    float* dWhhP    = carve((size_t)64 * 3072);
    float* dWihP    = carve((size_t)160 * 3072);
    float* WhP      = carve((size_t)64 * 1024);
    float* fcP      = carve((size_t)128 * 1024);
    float* WeP      = carve((size_t)128 * 1024);
    __half* Bh = hb;
    __half* Ah = hb + 28672000;

    cudaMemsetAsync(bar, 0, 4 * sizeof(unsigned));

    // (a) zero row-0 of outputs
    zero_out_kernel<<<8000, 256>>>(out);
    // (b) prologue: fc_W->fp16, embed, pack4 weight transposes
    prologue_kernel<<<119552, 256>>>(fc_W, Bh, src, enc_emb, emb,
                                     enc_Whh_f, WhhP_f, enc_Whh_b, WhhP_b,
                                     dec_Whh, dWhhP, dec_Wih, dWihP,
                                     attn_W, WhP, enc_fc_W, fcP, WeP);
    // (c) both input-gate GEMMs
    sgemm_gi_kernel<<<dim3(6, 64, 2), 256>>>(emb, enc_Wih_f, enc_Wih_b,
                                             enc_bih_f, enc_bih_b, gi_f, gi_b);
    // (d) persistent encoder (+enc_proj tail)
    enc_fused_kernel<<<128, 256>>>(WhhP_f, WhhP_b, enc_bhh_f, enc_bhh_b,
                                   gi_f, gi_b, h_enc, enc_outs,
                                   WeP, attn_b, enc_proj, bar);
    // (e) persistent decoder (+enc_fc init, +fp16 convert tail)
    dec_fused_kernel<<<64, 256>>>(trg, dec_emb, WhP, attn_v, enc_proj, enc_outs,
                                  dWihP, dWhhP, dec_bih, dec_bhh, h_enc, fcP, enc_fc_b,
                                  dec_h, xbuf, fc_in, Ah, bar + 3);
    // (f) fc: fp16 tensor-core GEMM, 4-stage pipeline
    cudaFuncSetAttribute(fc_mma_kernel, cudaFuncAttributeMaxDynamicSharedMemorySize,
                         4 * FC_STAGE);
    fc_mma_kernel<<<dim3(32, 250), 256, 4 * FC_STAGE>>>(Ah, Bh, fc_b,
                                                        out + (size_t)64 * 32000);
}